// round 3
// baseline (speedup 1.0000x reference)
#include <cuda_runtime.h>
#include <cstdint>

#define Sn 3
#define Bn 8
#define Kk 11
#define Cc 23
#define Hh 256
#define Ww 256
#define HW 65536
#define CHA 4                // chunks per (s,b,k)
#define NBLK (Sn*Bn*Kk)      // 264
#define TOTB (NBLK*CHA)      // 1056 blocks

// scratch (no device-side allocation allowed)
__device__ float              g_heatpart[TOTB];
__device__ unsigned long long g_ampart  [TOTB];
__device__ float              g_maskpart[TOTB];
__device__ unsigned int       g_count;          // zero-init; reset by last block

__device__ __forceinline__ float warpSum(float v) {
    #pragma unroll
    for (int o = 16; o > 0; o >>= 1) v += __shfl_down_sync(0xFFFFFFFFu, v, o);
    return v;
}
__device__ __forceinline__ unsigned long long warpMaxU64(unsigned long long v) {
    #pragma unroll
    for (int o = 16; o > 0; o >>= 1) {
        unsigned long long u = __shfl_down_sync(0xFFFFFFFFu, v, o);
        if (u > v) v = u;
    }
    return v;
}
__device__ __forceinline__ float bce_fast(float p, float g) {
    float lp  = fmaxf(__logf(p),        -100.0f);
    float l1p = fmaxf(__logf(1.0f - p), -100.0f);
    return -(g * lp + (1.0f - g) * l1p);
}

// grid (NBLK, CHA), 256 threads. Streaming MSE + argmax + a 1/Kk slice of the
// mask-BCE per block; last block to finish does the full finalization.
__global__ void __launch_bounds__(256)
fused_kernel(const float* __restrict__ cp,     // combined_preds (S,B,C,H,W)
             const float* __restrict__ hm,     // heatmaps       (S,B,K,H,W)
             const float* __restrict__ labels, // (B,K,7)
             const float* __restrict__ mask,   // masks          (S,B,1,H,W)
             float* __restrict__ out)
{
    const int sbk   = blockIdx.x;        // 0..263
    const int chunk = blockIdx.y;        // 0..CHA-1
    const int k  = sbk % Kk;
    const int sb = sbk / Kk;             // s*B + b

    const float4* __restrict__ hp = (const float4*)(cp + ((size_t)sb * Cc + (Kk + k)) * HW);
    const float4* __restrict__ hh = (const float4*)(hm + ((size_t)sb * Kk + k) * HW);
    const float4* __restrict__ mm = (const float4*)(mask + (size_t)sb * HW);

    const int QPC  = HW / 4 / CHA;       // 4096 float4 per chunk
    const int base = chunk * QPC;

    float sum = 0.0f;
    float bv  = -1.0f;
    int   bi  = 0;

    #pragma unroll 4
    for (int i = threadIdx.x; i < QPC; i += 256) {
        float4 a = hp[base + i];
        float4 h = hh[base + i];
        float4 m = mm[base + i];
        int p = (base + i) * 4;
        float d;
        d = fmaf(a.x, m.x, -h.x); sum = fmaf(d, d, sum); if (h.x > bv) { bv = h.x; bi = p;     }
        d = fmaf(a.y, m.y, -h.y); sum = fmaf(d, d, sum); if (h.y > bv) { bv = h.y; bi = p + 1; }
        d = fmaf(a.z, m.z, -h.z); sum = fmaf(d, d, sum); if (h.z > bv) { bv = h.z; bi = p + 2; }
        d = fmaf(a.w, m.w, -h.w); sum = fmaf(d, d, sum); if (h.w > bv) { bv = h.w; bi = p + 3; }
    }

    unsigned long long pk = 0ULL;
    if (bv >= 0.0f)
        pk = ((unsigned long long)__float_as_uint(bv) << 32) |
             (unsigned long long)(0xFFFFFFFFu - (unsigned)bi);

    // mask BCE slice: contiguous [start, start+cnt) of this chunk's pixels
    const int elems = HW / CHA;                 // 16384
    const int per   = elems / Kk;               // 1489
    const int rem   = elems % Kk;               // 5
    const int start = chunk * elems + k * per + min(k, rem);
    const int cnt   = per + (k < rem ? 1 : 0);
    const float* __restrict__ mp = cp   + ((size_t)sb * Cc + 2 * Kk) * HW;
    const float* __restrict__ mk = mask + (size_t)sb * HW;
    float msum = 0.0f;
    for (int i = threadIdx.x; i < cnt; i += 256)
        msum += bce_fast(mp[start + i], mk[start + i]);

    // block reduce all three
    sum  = warpSum(sum);
    msum = warpSum(msum);
    pk   = warpMaxU64(pk);

    __shared__ float s1[8], s3[8];
    __shared__ unsigned long long s2[8];
    __shared__ bool sh_last;
    int w = threadIdx.x >> 5, l = threadIdx.x & 31;
    if (l == 0) { s1[w] = sum; s2[w] = pk; s3[w] = msum; }
    __syncthreads();
    if (w == 0) {
        sum  = (l < 8) ? s1[l] : 0.0f;
        pk   = (l < 8) ? s2[l] : 0ULL;
        msum = (l < 8) ? s3[l] : 0.0f;
        sum  = warpSum(sum);
        msum = warpSum(msum);
        pk   = warpMaxU64(pk);
        if (l == 0) {
            const int slot = sbk * CHA + chunk;
            g_heatpart[slot] = sum;
            g_ampart  [slot] = pk;
            g_maskpart[slot] = msum;
            __threadfence();
            unsigned int t = atomicAdd(&g_count, 1u);
            sh_last = (t == (unsigned)(TOTB - 1));
        }
    }
    __syncthreads();
    if (!sh_last) return;

    // ---------------- finalize (last block only) ----------------
    __shared__ float sh_heat[NBLK];
    __shared__ float sh_bce [NBLK];
    const int tid = threadIdx.x;

    for (int t = tid; t < NBLK; t += 256) {
        float hs = 0.0f;
        unsigned long long mpk = 0ULL;
        #pragma unroll
        for (int c = 0; c < CHA; c++) {
            hs += g_heatpart[t * CHA + c];
            unsigned long long v = g_ampart[t * CHA + c];
            if (v > mpk) mpk = v;
        }
        sh_heat[t] = hs;

        unsigned idx  = 0xFFFFFFFFu - (unsigned)(mpk & 0xFFFFFFFFu);
        float    peak = __uint_as_float((unsigned)(mpk >> 32));
        int kk  = t % Kk;
        int tsb = t / Kk;
        int b   = tsb % Bn;
        int lin = (int)(idx / Hh) * Ww + (int)(idx % Hh);

        float bce = 0.0f;
        if (peak == 1.0f) {
            #pragma unroll
            for (int c = 0; c < 7; c++) {
                float p = cp[((size_t)tsb * Cc + c) * HW + lin];
                float g = labels[(b * Kk + kk) * 7 + c];
                float lp  = fmaxf(__logf(p),        -100.0f);
                float l1p = fmaxf(__logf(1.0f - p), -100.0f);
                bce += -(g * lp + (1.0f - g) * l1p);
            }
            bce *= (1.0f / 7.0f);
        }
        sh_bce[t] = bce;
    }
    __syncthreads();

    if (tid < Sn * Bn) {          // tid == sb
        float hsum = 0.0f, bsum = 0.0f;
        #pragma unroll
        for (int kk = 0; kk < Kk; kk++) {
            hsum += sh_heat[tid * Kk + kk];
            bsum += sh_bce [tid * Kk + kk];
        }
        float msum2 = 0.0f;
        #pragma unroll
        for (int j = 0; j < Kk * CHA; j++)
            msum2 += g_maskpart[tid * (Kk * CHA) + j];

        int b = tid % Bn, s = tid / Bn;
        out[          b * Sn + s] = hsum * (1.0f / Kk);
        out[Sn * Bn + b * Sn + s] = bsum * (1.0f / Kk);
        out[2*Sn*Bn + b * Sn + s] = msum2 * (1.0f / (float)HW);
    }
    if (tid == 0) g_count = 0;   // reset for next launch / graph replay
}

extern "C" void kernel_launch(void* const* d_in, const int* in_sizes, int n_in,
                              void* d_out, int out_size)
{
    const float* cp     = (const float*)d_in[0];   // combined_preds
    const float* hm     = (const float*)d_in[1];   // heatmaps
    const float* labels = (const float*)d_in[2];   // labels
    const float* mask   = (const float*)d_in[3];   // masks
    float* out = (float*)d_out;

    dim3 grid(NBLK, CHA);
    fused_kernel<<<grid, 256>>>(cp, hm, labels, mask, out);
}

// round 6
// speedup vs baseline: 1.1765x; 1.1765x over previous
#include <cuda_runtime.h>
#include <cstdint>

#define Sn 3
#define Bn 8
#define Kk 11
#define Cc 23
#define Hh 256
#define Ww 256
#define HW 65536
#define CHA 4                // chunks per (s,b,k)
#define NBLK (Sn*Bn*Kk)      // 264

// scratch (no device-side allocation allowed)
__device__ float              g_heatpart[NBLK * CHA];
__device__ unsigned long long g_ampart  [NBLK * CHA];
__device__ float              g_maskpart[NBLK * CHA];

__device__ __forceinline__ float warpSum(float v) {
    #pragma unroll
    for (int o = 16; o > 0; o >>= 1) v += __shfl_down_sync(0xFFFFFFFFu, v, o);
    return v;
}
__device__ __forceinline__ unsigned long long warpMaxU64(unsigned long long v) {
    #pragma unroll
    for (int o = 16; o > 0; o >>= 1) {
        unsigned long long u = __shfl_down_sync(0xFFFFFFFFu, v, o);
        if (u > v) v = u;
    }
    return v;
}
__device__ __forceinline__ float bce_fast(float p, float g) {
    float lp  = fmaxf(__logf(p),        -100.0f);
    float l1p = fmaxf(__logf(1.0f - p), -100.0f);
    return -(g * lp + (1.0f - g) * l1p);
}

// grid (NBLK, CHA), 256 threads. Loads front-batched (a[4],h[4],m[4]) so ptxas
// emits 12 consecutive LDG.128 per warp-iteration -> high MLP.
__global__ void __launch_bounds__(256)
main_kernel(const float* __restrict__ cp,     // combined_preds (S,B,C,H,W)
            const float* __restrict__ hm,     // heatmaps       (S,B,K,H,W)
            const float* __restrict__ mask)   // masks          (S,B,1,H,W)
{
    const int sbk   = blockIdx.x;        // 0..263
    const int chunk = blockIdx.y;        // 0..CHA-1
    const int k  = sbk % Kk;
    const int sb = sbk / Kk;             // s*B + b

    const float4* __restrict__ hp = (const float4*)(cp + ((size_t)sb * Cc + (Kk + k)) * HW);
    const float4* __restrict__ hh = (const float4*)(hm + ((size_t)sb * Kk + k) * HW);
    const float4* __restrict__ mm = (const float4*)(mask + (size_t)sb * HW);

    const int QPC  = HW / 4 / CHA;       // 4096 float4 per chunk
    const int base = chunk * QPC;
    const int t    = threadIdx.x;

    float sum = 0.0f;
    float bv  = -1.0f;
    int   bi  = 0;

    // QPC = 4096 = 4 outer iters * 4 inner * 256 threads
    #pragma unroll 1
    for (int o = 0; o < QPC; o += 256 * 4) {
        float4 a[4], h[4], m[4];
        int id0 = base + o + t;
        #pragma unroll
        for (int u = 0; u < 4; u++) a[u] = hp[id0 + u * 256];
        #pragma unroll
        for (int u = 0; u < 4; u++) h[u] = hh[id0 + u * 256];
        #pragma unroll
        for (int u = 0; u < 4; u++) m[u] = mm[id0 + u * 256];
        #pragma unroll
        for (int u = 0; u < 4; u++) {
            int p = (id0 + u * 256) * 4;
            float d;
            d = fmaf(a[u].x, m[u].x, -h[u].x); sum = fmaf(d, d, sum); if (h[u].x > bv) { bv = h[u].x; bi = p;     }
            d = fmaf(a[u].y, m[u].y, -h[u].y); sum = fmaf(d, d, sum); if (h[u].y > bv) { bv = h[u].y; bi = p + 1; }
            d = fmaf(a[u].z, m[u].z, -h[u].z); sum = fmaf(d, d, sum); if (h[u].z > bv) { bv = h[u].z; bi = p + 2; }
            d = fmaf(a[u].w, m[u].w, -h[u].w); sum = fmaf(d, d, sum); if (h[u].w > bv) { bv = h[u].w; bi = p + 3; }
        }
    }

    unsigned long long pk = 0ULL;
    if (bv >= 0.0f)
        pk = ((unsigned long long)__float_as_uint(bv) << 32) |
             (unsigned long long)(0xFFFFFFFFu - (unsigned)bi);

    // mask BCE slice: contiguous [start, start+cnt) of this chunk's pixels
    const int elems = HW / CHA;                 // 16384
    const int per   = elems / Kk;               // 1489
    const int rem   = elems % Kk;               // 5
    const int start = chunk * elems + k * per + min(k, rem);
    const int cnt   = per + (k < rem ? 1 : 0);
    const float* __restrict__ mp = cp   + ((size_t)sb * Cc + 2 * Kk) * HW;
    const float* __restrict__ mk = mask + (size_t)sb * HW;
    float msum = 0.0f;
    for (int i = t; i < cnt; i += 256)
        msum += bce_fast(mp[start + i], mk[start + i]);

    // block reduce all three
    sum  = warpSum(sum);
    msum = warpSum(msum);
    pk   = warpMaxU64(pk);

    __shared__ float s1[8], s3[8];
    __shared__ unsigned long long s2[8];
    int w = t >> 5, l = t & 31;
    if (l == 0) { s1[w] = sum; s2[w] = pk; s3[w] = msum; }
    __syncthreads();
    if (w == 0) {
        sum  = (l < 8) ? s1[l] : 0.0f;
        pk   = (l < 8) ? s2[l] : 0ULL;
        msum = (l < 8) ? s3[l] : 0.0f;
        sum  = warpSum(sum);
        msum = warpSum(msum);
        pk   = warpMaxU64(pk);
        if (l == 0) {
            g_heatpart[sbk * CHA + chunk] = sum;
            g_ampart  [sbk * CHA + chunk] = pk;
            g_maskpart[sbk * CHA + chunk] = msum;
        }
    }
}

// 1 block, 288 threads. Gathers batched: all 7 scattered loads issue before
// any log math so they overlap in one DRAM round-trip.
__global__ void __launch_bounds__(288)
finalize_kernel(const float* __restrict__ cp,
                const float* __restrict__ labels,   // (B,K,7)
                float* __restrict__ out)
{
    __shared__ float sh_heat[NBLK];
    __shared__ float sh_bce [NBLK];
    int t = threadIdx.x;

    if (t < NBLK) {
        float hs = 0.0f;
        unsigned long long pk = 0ULL;
        #pragma unroll
        for (int c = 0; c < CHA; c++) {
            hs += g_heatpart[t * CHA + c];
            unsigned long long v = g_ampart[t * CHA + c];
            if (v > pk) pk = v;
        }
        sh_heat[t] = hs;

        unsigned idx  = 0xFFFFFFFFu - (unsigned)(pk & 0xFFFFFFFFu);
        float    peak = __uint_as_float((unsigned)(pk >> 32));
        int k  = t % Kk;
        int sb = t / Kk;
        int b  = sb % Bn;
        int lin = (int)(idx / Hh) * Ww + (int)(idx % Hh);

        float bce = 0.0f;
        if (peak == 1.0f) {
            float p[7], g[7];
            #pragma unroll
            for (int c = 0; c < 7; c++) p[c] = __ldg(&cp[((size_t)sb * Cc + c) * HW + lin]);
            #pragma unroll
            for (int c = 0; c < 7; c++) g[c] = labels[(b * Kk + k) * 7 + c];
            #pragma unroll
            for (int c = 0; c < 7; c++) {
                float lp  = fmaxf(__logf(p[c]),        -100.0f);
                float l1p = fmaxf(__logf(1.0f - p[c]), -100.0f);
                bce += -(g[c] * lp + (1.0f - g[c]) * l1p);
            }
            bce *= (1.0f / 7.0f);
        }
        sh_bce[t] = bce;
    }
    __syncthreads();

    if (t < Sn * Bn) {          // t == sb
        float hsum = 0.0f, bsum = 0.0f;
        #pragma unroll
        for (int k = 0; k < Kk; k++) {
            hsum += sh_heat[t * Kk + k];
            bsum += sh_bce [t * Kk + k];
        }
        float msum = 0.0f;
        #pragma unroll
        for (int j = 0; j < Kk * CHA; j++)
            msum += g_maskpart[t * (Kk * CHA) + j];

        int b = t % Bn, s = t / Bn;
        out[          b * Sn + s] = hsum * (1.0f / Kk);
        out[Sn * Bn + b * Sn + s] = bsum * (1.0f / Kk);
        out[2*Sn*Bn + b * Sn + s] = msum * (1.0f / (float)HW);
    }
}

extern "C" void kernel_launch(void* const* d_in, const int* in_sizes, int n_in,
                              void* d_out, int out_size)
{
    const float* cp     = (const float*)d_in[0];   // combined_preds
    const float* hm     = (const float*)d_in[1];   // heatmaps
    const float* labels = (const float*)d_in[2];   // labels
    const float* mask   = (const float*)d_in[3];   // masks
    float* out = (float*)d_out;

    dim3 grid(NBLK, CHA);
    main_kernel<<<grid, 256>>>(cp, hm, mask);
    finalize_kernel<<<1, 288>>>(cp, labels, out);
}